// round 1
// baseline (speedup 1.0000x reference)
#include <cuda_runtime.h>
#include <math.h>

#define TOPK 20
#define NEMAX (2*15488)
#define HWMAX (2*1936)

__device__ float g_a[NEMAX];
__device__ float g_S[NEMAX];
__device__ float g_pos[HWMAX];
__device__ float g_topv[HWMAX*TOPK];
__device__ int   g_topi[HWMAX*TOPK];
__device__ float g_em1[HWMAX*TOPK];
__device__ float g_U[32];

__device__ __forceinline__ float gelu_exact(float x){
    return 0.5f * x * (1.0f + erff(x * 0.7071067811865475f));
}

// K1: a[b,n] = sum_c km^2 ; S init to HW
__global__ void k1_prep(const float* __restrict__ km, int NE, int HW){
    int idx = blockIdx.x*blockDim.x + threadIdx.x;
    if (idx >= 2*NE) return;
    int b = idx / NE, n = idx - b*NE;
    const float* p = km + (size_t)b*64*NE + n;
    float s = 0.f;
    #pragma unroll
    for (int c=0;c<64;c++){ float v = p[(size_t)c*NE]; s += v*v; }
    g_a[idx] = s;
    g_S[idx] = (float)HW;
}

// K2: pos_w[b,h] = softmax(score/0.1) ; one block per batch
__global__ void __launch_bounds__(256) k2_posw(
    const float* __restrict__ vq,
    const float* __restrict__ w1, const float* __restrict__ b1,
    const float* __restrict__ w2, const float* __restrict__ b2,
    const float* __restrict__ lg, const float* __restrict__ lb,
    const float* __restrict__ pw1, const float* __restrict__ pb1,
    const float* __restrict__ pw2, const float* __restrict__ pb2,
    int HW, int scale)
{
    int b = blockIdx.x;
    int tid = threadIdx.x;
    __shared__ float red[256];
    __shared__ float pooled[16];
    __shared__ float cwp[16][8];
    __shared__ float sb1[8];
    const float* v = vq + (size_t)b*16*HW;

    // pooled mean over HW
    int c = tid & 15;
    float s = 0.f;
    for (int h = tid>>4; h < HW; h += 16) s += v[(size_t)c*HW + h];
    red[tid] = s;
    __syncthreads();
    for (int st=128; st>=16; st>>=1){
        if (tid < st) red[tid] += red[tid+st];
        __syncthreads();
    }
    if (tid < 16) pooled[tid] = red[tid] / (float)HW;
    __syncthreads();

    if (tid == 0){
        float t = b1[scale];
        for (int i=0;i<16;i++) t += pooled[i]*w1[scale*16+i];
        t = gelu_exact(t);
        float cw[16]; float m = 0.f;
        for (int i=0;i<16;i++){ cw[i] = t*w2[scale*16+i] + b2[scale*16+i]; m += cw[i]; }
        m *= (1.f/16.f);
        float var = 0.f;
        for (int i=0;i<16;i++){ float d = cw[i]-m; var += d*d; }
        var *= (1.f/16.f);
        float r = rsqrtf(var + 1e-5f);
        for (int i=0;i<16;i++){
            float cn = (cw[i]-m)*r*lg[scale*16+i] + lb[scale*16+i];
            for (int j=0;j<8;j++) cwp[i][j] = cn * pw1[scale*128 + i*8 + j];
        }
        for (int j=0;j<8;j++) sb1[j] = pb1[scale*8+j];
    }
    __syncthreads();

    // scores
    float lmax = -3.4e38f;
    for (int h = tid; h < HW; h += 256){
        float hj[8];
        #pragma unroll
        for (int j=0;j<8;j++) hj[j] = sb1[j];
        #pragma unroll
        for (int i=0;i<16;i++){
            float x = v[(size_t)i*HW + h];
            #pragma unroll
            for (int j=0;j<8;j++) hj[j] += x * cwp[i][j];
        }
        float sc = pb2[scale];
        #pragma unroll
        for (int j=0;j<8;j++) sc += gelu_exact(hj[j]) * pw2[scale*8+j];
        g_pos[b*HW + h] = sc;
        lmax = fmaxf(lmax, sc);
    }
    red[tid] = lmax;
    __syncthreads();
    for (int st=128; st>=1; st>>=1){
        if (tid<st) red[tid] = fmaxf(red[tid], red[tid+st]);
        __syncthreads();
    }
    float m = red[0];
    __syncthreads();

    float lsum = 0.f;
    for (int h = tid; h < HW; h += 256){
        float p = expf((g_pos[b*HW+h] - m)*10.0f);
        g_pos[b*HW+h] = p;
        lsum += p;
    }
    red[tid] = lsum;
    __syncthreads();
    for (int st=128; st>=1; st>>=1){
        if (tid<st) red[tid] += red[tid+st];
        __syncthreads();
    }
    float inv = 1.0f/red[0];
    __syncthreads();
    for (int h = tid; h < HW; h += 256) g_pos[b*HW+h] *= inv;
}

__device__ __forceinline__ void ins20(float v, int i, float tv[TOPK], int ti[TOPK]){
    if (v > tv[0]){
        tv[0] = v; ti[0] = i;
        #pragma unroll
        for (int s=0;s<TOPK-1;s++){
            if (tv[s] > tv[s+1]){
                float a = tv[s]; tv[s] = tv[s+1]; tv[s+1] = a;
                int x = ti[s]; ti[s] = ti[s+1]; ti[s+1] = x;
            }
        }
    }
}

// K3: fused affinity GEMM (K=64) + per-column top-20 over NE
// block: 256 threads = 32 columns x 8 n-subgroups ; n-tile = 32
__global__ void __launch_bounds__(256) k3_topk(
    const float* __restrict__ kq, const float* __restrict__ km, int NE, int HW)
{
    __shared__ __align__(16) char smem[41984];
    float (*qk_s)[32] = reinterpret_cast<float(*)[32]>(smem);          // 8KB
    float (*km_s)[32] = reinterpret_cast<float(*)[32]>(smem + 8192);   // 8KB
    float* a_s = reinterpret_cast<float*>(smem + 16384);               // 128B

    int b = blockIdx.y;
    int h0 = blockIdx.x * 32;
    int tid = threadIdx.x;
    int col = tid & 31;
    int nsub = tid >> 5;
    int h = h0 + col;

    // load qk tile [64][32]
    for (int i = tid; i < 64*32; i += 256){
        int c = i >> 5, cc = i & 31;
        int hg = h0 + cc;
        qk_s[c][cc] = (hg < HW) ? kq[((size_t)b*64 + c)*HW + hg] : 0.f;
    }

    float tv[TOPK]; int ti[TOPK];
    #pragma unroll
    for (int k=0;k<TOPK;k++){ tv[k] = -3.4e38f; ti[k] = 0; }

    int nTiles = (NE + 31) >> 5;
    int nb = nsub << 2;
    for (int t = 0; t < nTiles; t++){
        int n0 = t << 5;
        __syncthreads();
        for (int i = tid; i < 64*32; i += 256){
            int c = i >> 5, nn = i & 31;
            int n = n0 + nn;
            km_s[c][nn] = (n < NE) ? km[((size_t)b*64 + c)*NE + n] : 0.f;
        }
        if (tid < 32){
            int n = n0 + tid;
            a_s[tid] = (n < NE) ? g_a[b*NE + n] : 0.f;
        }
        __syncthreads();

        float acc0=0.f, acc1=0.f, acc2=0.f, acc3=0.f;
        #pragma unroll
        for (int c=0;c<64;c++){
            float4 k4 = *reinterpret_cast<const float4*>(&km_s[c][nb]);
            float q = qk_s[c][col];
            acc0 += k4.x*q; acc1 += k4.y*q; acc2 += k4.z*q; acc3 += k4.w*q;
        }
        float4 a4 = *reinterpret_cast<const float4*>(&a_s[nb]);
        int n = n0 + nb;
        float f0 = acc0*0.25f - 0.125f*a4.x;
        float f1 = acc1*0.25f - 0.125f*a4.y;
        float f2 = acc2*0.25f - 0.125f*a4.z;
        float f3 = acc3*0.25f - 0.125f*a4.w;
        if (n+0 < NE) ins20(f0, n+0, tv, ti);
        if (n+1 < NE) ins20(f1, n+1, tv, ti);
        if (n+2 < NE) ins20(f2, n+2, tv, ti);
        if (n+3 < NE) ins20(f3, n+3, tv, ti);
    }

    // merge 8 partial top-20 lists per column
    __syncthreads();
    float* mv = reinterpret_cast<float*>(smem);           // [32][160] 20KB
    int*   mi = reinterpret_cast<int*>(smem + 20480);     // [32][160] 20KB
    #pragma unroll
    for (int k=0;k<TOPK;k++){
        mv[col*160 + nsub*TOPK + k] = tv[k];
        mi[col*160 + nsub*TOPK + k] = ti[k];
    }
    __syncthreads();
    if (nsub == 0 && h < HW){
        int head[8];
        #pragma unroll
        for (int j=0;j<8;j++) head[j] = TOPK-1;
        float* cv = mv + col*160;
        int*   ci = mi + col*160;
        int base = (b*HW + h)*TOPK;
        for (int k=0;k<TOPK;k++){
            float best = -3.4e38f; int bj = 0;
            #pragma unroll
            for (int j=0;j<8;j++){
                float v = cv[j*TOPK + head[j]];
                if (v > best){ best = v; bj = j; }
            }
            g_topv[base+k] = best;
            g_topi[base+k] = ci[bj*TOPK + head[bj]];
            head[bj]--;
        }
    }
}

// K4: per-column softmax over top-20, x = w*pos_w, em1 = expm1(x), scatter-add to S
__global__ void k4_scatter(int NE, int HW){
    int idx = blockIdx.x*blockDim.x + threadIdx.x;
    if (idx >= 2*HW) return;
    int b = idx / HW;
    const float* tvp = g_topv + (size_t)idx*TOPK;
    const int*   tip = g_topi + (size_t)idx*TOPK;
    float v[TOPK]; int id[TOPK];
    #pragma unroll
    for (int k=0;k<TOPK;k++){ v[k] = tvp[k]; id[k] = tip[k]; }
    float m = v[0];
    #pragma unroll
    for (int k=1;k<TOPK;k++) m = fmaxf(m, v[k]);
    float ssum = 0.f; float e[TOPK];
    #pragma unroll
    for (int k=0;k<TOPK;k++){ e[k] = expf(v[k]-m); ssum += e[k]; }
    float scale = g_pos[idx] / ssum;
    #pragma unroll
    for (int k=0;k<TOPK;k++){
        float em1 = expm1f(e[k]*scale);
        g_em1[(size_t)idx*TOPK + k] = em1;
        atomicAdd(&g_S[b*NE + id[k]], em1);
    }
}

// K5: U[b,c] = sum_n vm[b,c,n] / S[b,n]
__global__ void __launch_bounds__(256) k5_U(const float* __restrict__ vm, int NE){
    int b = blockIdx.x >> 4;
    int c = blockIdx.x & 15;
    __shared__ float red[256];
    const float* p  = vm + ((size_t)b*16 + c)*NE;
    const float* Sp = g_S + b*NE;
    float s = 0.f;
    for (int n = threadIdx.x; n < NE; n += 256) s += p[n] / Sp[n];
    red[threadIdx.x] = s;
    __syncthreads();
    for (int st=128; st>=1; st>>=1){
        if (threadIdx.x < st) red[threadIdx.x] += red[threadIdx.x+st];
        __syncthreads();
    }
    if (threadIdx.x == 0) g_U[b*16+c] = red[0];
}

// K6: readout = U + sparse gather ; concat vq
__global__ void k6_out(const float* __restrict__ vm, const float* __restrict__ vq,
                       float* __restrict__ out, int NE, int HW){
    int idx = blockIdx.x*blockDim.x + threadIdx.x;
    if (idx >= 2*HW) return;
    int b = idx / HW, h = idx - b*HW;
    float acc[16];
    #pragma unroll
    for (int c=0;c<16;c++) acc[c] = g_U[b*16+c];
    #pragma unroll
    for (int k=0;k<TOPK;k++){
        int n = g_topi[(size_t)idx*TOPK + k];
        float f = g_em1[(size_t)idx*TOPK + k] / g_S[b*NE + n];
        const float* vp = vm + (size_t)b*16*NE + n;
        #pragma unroll
        for (int c=0;c<16;c++) acc[c] += vp[(size_t)c*NE]*f;
    }
    float* o = out + (size_t)b*32*HW + h;
    const float* v = vq + (size_t)b*16*HW + h;
    #pragma unroll
    for (int c=0;c<16;c++){
        o[(size_t)c*HW] = acc[c];
        o[(size_t)(16+c)*HW] = v[(size_t)c*HW];
    }
}

extern "C" void kernel_launch(void* const* d_in, const int* in_sizes, int n_in,
                              void* d_out, int out_size){
    const float* w1  = (const float*)d_in[12];
    const float* b1  = (const float*)d_in[13];
    const float* w2  = (const float*)d_in[14];
    const float* b2  = (const float*)d_in[15];
    const float* lg  = (const float*)d_in[16];
    const float* lb  = (const float*)d_in[17];
    const float* pw1 = (const float*)d_in[18];
    const float* pb1 = (const float*)d_in[19];
    const float* pw2 = (const float*)d_in[20];
    const float* pb2 = (const float*)d_in[21];

    size_t ooff = 0;
    for (int i=0;i<3;i++){
        const float* kq = (const float*)d_in[i*4+0];
        const float* vq = (const float*)d_in[i*4+1];
        const float* km = (const float*)d_in[i*4+2];
        const float* vm = (const float*)d_in[i*4+3];
        int HW = in_sizes[i*4+0] / (2*64);   // [B=2, 64, H, W]
        int NE = in_sizes[i*4+2] / (2*64);   // [B=2, 64, NE]

        float* out = (float*)d_out + ooff;

        k1_prep<<<(2*NE + 255)/256, 256>>>(km, NE, HW);
        k2_posw<<<2, 256>>>(vq, w1,b1,w2,b2,lg,lb,pw1,pb1,pw2,pb2, HW, i);
        dim3 g3((HW + 31)/32, 2);
        k3_topk<<<g3, 256>>>(kq, km, NE, HW);
        k4_scatter<<<(2*HW + 127)/128, 128>>>(NE, HW);
        k5_U<<<32, 256>>>(vm, NE);
        k6_out<<<(2*HW + 127)/128, 128>>>(vm, vq, out, NE, HW);

        ooff += (size_t)2*32*HW;
    }
}

// round 4
// speedup vs baseline: 1.9043x; 1.9043x over previous
#include <cuda_runtime.h>
#include <math.h>

#define TOPK 20
#define NEMAX (2*15488)
#define HWMAX (2*1936)
#define LISTS_MAX (16*2*1936)

__device__ float g_a[NEMAX];          // 0.125 * sum km^2
__device__ float g_S[NEMAX];
__device__ float g_pos[HWMAX];
__device__ int   g_topi[HWMAX*TOPK];
__device__ float g_em1[HWMAX*TOPK];
__device__ float g_U[32];
__device__ float g_pv[LISTS_MAX*TOPK];
__device__ int   g_pi[LISTS_MAX*TOPK];

__device__ __forceinline__ float gelu_exact(float x){
    return 0.5f * x * (1.0f + erff(x * 0.7071067811865475f));
}

__global__ void k0_dummy(){ if (threadIdx.x < 32) g_U[threadIdx.x] = 0.f; }

// K1: a[b,n] = 0.125*sum_c km^2 ; S init to HW
__global__ void k1_prep(const float* __restrict__ km, int NE, int HW){
    int idx = blockIdx.x*blockDim.x + threadIdx.x;
    if (idx >= 2*NE) return;
    int b = idx / NE, n = idx - b*NE;
    const float* p = km + (size_t)b*64*NE + n;
    float s = 0.f;
    #pragma unroll
    for (int c=0;c<64;c++){ float v = p[(size_t)c*NE]; s += v*v; }
    g_a[idx] = 0.125f*s;
    g_S[idx] = (float)HW;
}

// K2: pos_w[b,h] = softmax(score/0.1)
__global__ void __launch_bounds__(256) k2_posw(
    const float* __restrict__ vq,
    const float* __restrict__ w1, const float* __restrict__ b1,
    const float* __restrict__ w2, const float* __restrict__ b2,
    const float* __restrict__ lg, const float* __restrict__ lb,
    const float* __restrict__ pw1, const float* __restrict__ pb1,
    const float* __restrict__ pw2, const float* __restrict__ pb2,
    int HW, int scale)
{
    int b = blockIdx.x;
    int tid = threadIdx.x;
    __shared__ float red[256];
    __shared__ float pooled[16];
    __shared__ float cwp[16][8];
    __shared__ float sb1[8];
    const float* v = vq + (size_t)b*16*HW;

    int c = tid & 15;
    float s = 0.f;
    for (int h = tid>>4; h < HW; h += 16) s += v[(size_t)c*HW + h];
    red[tid] = s;
    __syncthreads();
    for (int st=128; st>=16; st>>=1){
        if (tid < st) red[tid] += red[tid+st];
        __syncthreads();
    }
    if (tid < 16) pooled[tid] = red[tid] / (float)HW;
    __syncthreads();

    if (tid == 0){
        float t = b1[scale];
        for (int i=0;i<16;i++) t += pooled[i]*w1[scale*16+i];
        t = gelu_exact(t);
        float cw[16]; float m = 0.f;
        for (int i=0;i<16;i++){ cw[i] = t*w2[scale*16+i] + b2[scale*16+i]; m += cw[i]; }
        m *= (1.f/16.f);
        float var = 0.f;
        for (int i=0;i<16;i++){ float d = cw[i]-m; var += d*d; }
        var *= (1.f/16.f);
        float r = rsqrtf(var + 1e-5f);
        for (int i=0;i<16;i++){
            float cn = (cw[i]-m)*r*lg[scale*16+i] + lb[scale*16+i];
            for (int j=0;j<8;j++) cwp[i][j] = cn * pw1[scale*128 + i*8 + j];
        }
        for (int j=0;j<8;j++) sb1[j] = pb1[scale*8+j];
    }
    __syncthreads();

    float lmax = -3.4e38f;
    for (int h = tid; h < HW; h += 256){
        float hj[8];
        #pragma unroll
        for (int j=0;j<8;j++) hj[j] = sb1[j];
        #pragma unroll
        for (int i=0;i<16;i++){
            float x = v[(size_t)i*HW + h];
            #pragma unroll
            for (int j=0;j<8;j++) hj[j] += x * cwp[i][j];
        }
        float sc = pb2[scale];
        #pragma unroll
        for (int j=0;j<8;j++) sc += gelu_exact(hj[j]) * pw2[scale*8+j];
        g_pos[b*HW + h] = sc;
        lmax = fmaxf(lmax, sc);
    }
    red[tid] = lmax;
    __syncthreads();
    for (int st=128; st>=1; st>>=1){
        if (tid<st) red[tid] = fmaxf(red[tid], red[tid+st]);
        __syncthreads();
    }
    float m = red[0];
    __syncthreads();

    float lsum = 0.f;
    for (int h = tid; h < HW; h += 256){
        float p = expf((g_pos[b*HW+h] - m)*10.0f);
        g_pos[b*HW+h] = p;
        lsum += p;
    }
    red[tid] = lsum;
    __syncthreads();
    for (int st=128; st>=1; st>>=1){
        if (tid<st) red[tid] += red[tid+st];
        __syncthreads();
    }
    float inv = 1.0f/red[0];
    __syncthreads();
    for (int h = tid; h < HW; h += 256) g_pos[b*HW+h] *= inv;
}

__device__ __forceinline__ void ins20(float v, int i, float tv[TOPK], int ti[TOPK]){
    if (v > tv[0]){
        tv[0] = v; ti[0] = i;
        #pragma unroll
        for (int s=0;s<TOPK-1;s++){
            if (tv[s] > tv[s+1]){
                float a = tv[s]; tv[s] = tv[s+1]; tv[s+1] = a;
                int x = ti[s]; ti[s] = ti[s+1]; ti[s+1] = x;
            }
        }
    }
}

// K3: fused affinity GEMM (K=64) + partial per-column top-20 over an NE chunk.
// block = 128 threads = 32 cols x 4 ngroups (8 n's each); n-tile = 32, double-buffered.
__global__ void __launch_bounds__(128) k3_topk(
    const float* __restrict__ kq, const float* __restrict__ km,
    int NE, int HW, int chunk)
{
    __shared__ __align__(16) char smem[24576];
    float (*qk_s)[32]    = reinterpret_cast<float(*)[32]>(smem);          // 8KB
    float (*km_s)[64][32]= reinterpret_cast<float(*)[64][32]>(smem + 8192); // 2x8KB

    int b  = blockIdx.y;
    int z  = blockIdx.z;
    int h0 = blockIdx.x * 32;
    int tid = threadIdx.x;
    int col = tid & 31;
    int ng  = tid >> 5;          // 0..3
    int nb  = ng << 3;           // 0,8,16,24
    int h = h0 + col;

    int n_begin = z * chunk;
    int n_end   = min(NE, n_begin + chunk);
    int ntiles  = (n_end > n_begin) ? ((n_end - n_begin + 31) >> 5) : 0;

    // load qk tile [64][32]
    for (int i = tid; i < 64*32; i += 128){
        int c = i >> 5, cc = i & 31;
        int hg = h0 + cc;
        qk_s[c][cc] = (hg < HW) ? kq[((size_t)b*64 + c)*HW + hg] : 0.f;
    }

    float tv[TOPK]; int ti[TOPK];
    #pragma unroll
    for (int k=0;k<TOPK;k++){ tv[k] = -3.4e38f; ti[k] = 0; }

    const float* kmb = km + (size_t)b*64*NE;
    const float* ab  = g_a + b*NE;

    // prefetch tile 0 into registers: 4 float4 per thread (f4 idx e = tid + i*128)
    float4 r[4];
    if (ntiles > 0){
        int n0 = n_begin;
        bool full = (n0 + 32 <= n_end);
        #pragma unroll
        for (int i=0;i<4;i++){
            int e = tid + i*128;            // float4 index in [0,512)
            int c = e >> 3, nn4 = (e & 7) << 2;
            if (full){
                r[i] = *reinterpret_cast<const float4*>(kmb + (size_t)c*NE + n0 + nn4);
            } else {
                float4 t; float* tp = (float*)&t;
                #pragma unroll
                for (int j=0;j<4;j++){
                    int n = n0 + nn4 + j;
                    tp[j] = (n < n_end) ? kmb[(size_t)c*NE + n] : 0.f;
                }
                r[i] = t;
            }
        }
    }

    for (int t = 0; t < ntiles; t++){
        int n0 = n_begin + (t << 5);
        int cur = t & 1;
        // store prefetched tile
        #pragma unroll
        for (int i=0;i<4;i++){
            int e = tid + i*128;
            int c = e >> 3, nn4 = (e & 7) << 2;
            *reinterpret_cast<float4*>(&km_s[cur][c][nn4]) = r[i];
        }
        __syncthreads();

        // prefetch next tile (LDG latency hidden under compute)
        if (t + 1 < ntiles){
            int n1 = n0 + 32;
            bool fulln = (n1 + 32 <= n_end);
            #pragma unroll
            for (int i=0;i<4;i++){
                int e = tid + i*128;
                int c = e >> 3, nn4 = (e & 7) << 2;
                if (fulln){
                    r[i] = *reinterpret_cast<const float4*>(kmb + (size_t)c*NE + n1 + nn4);
                } else {
                    float4 tt; float* tp = (float*)&tt;
                    #pragma unroll
                    for (int j=0;j<4;j++){
                        int n = n1 + nn4 + j;
                        tp[j] = (n < n_end) ? kmb[(size_t)c*NE + n] : 0.f;
                    }
                    r[i] = tt;
                }
            }
        }

        // a2 for this thread's 8 n's
        float4 a0 = *reinterpret_cast<const float4*>(ab + n0 + nb);
        float4 a1 = *reinterpret_cast<const float4*>(ab + n0 + nb + 4);

        float acc[8];
        #pragma unroll
        for (int j=0;j<8;j++) acc[j] = 0.f;

        // software-pipelined over c: q for c+1 loaded one iteration early
        float qcur = qk_s[0][col];
        #pragma unroll 16
        for (int c=0;c<64;c++){
            float qnext = (c < 63) ? qk_s[c+1][col] : 0.f;
            float4 k0 = *reinterpret_cast<const float4*>(&km_s[cur][c][nb]);
            float4 k1 = *reinterpret_cast<const float4*>(&km_s[cur][c][nb+4]);
            acc[0] += k0.x*qcur; acc[1] += k0.y*qcur; acc[2] += k0.z*qcur; acc[3] += k0.w*qcur;
            acc[4] += k1.x*qcur; acc[5] += k1.y*qcur; acc[6] += k1.z*qcur; acc[7] += k1.w*qcur;
            qcur = qnext;
        }

        int n = n0 + nb;
        float f[8];
        f[0] = 0.25f*acc[0] - a0.x; f[1] = 0.25f*acc[1] - a0.y;
        f[2] = 0.25f*acc[2] - a0.z; f[3] = 0.25f*acc[3] - a0.w;
        f[4] = 0.25f*acc[4] - a1.x; f[5] = 0.25f*acc[5] - a1.y;
        f[6] = 0.25f*acc[6] - a1.z; f[7] = 0.25f*acc[7] - a1.w;
        if (n0 + 32 > n_end){
            #pragma unroll
            for (int j=0;j<8;j++) if (n + j >= n_end) f[j] = -3.4e38f;
        }
        #pragma unroll
        for (int j=0;j<8;j++) ins20(f[j], n+j, tv, ti);

        __syncthreads();
    }

    // merge 4 partial lists per column, write partial top-20 to global
    __syncthreads();
    float* mv = reinterpret_cast<float*>(smem);            // [32][4][20] = 10240B
    int*   mi = reinterpret_cast<int*>(smem + 10240);      // 10240B
    #pragma unroll
    for (int k=0;k<TOPK;k++){
        mv[(col*4 + ng)*TOPK + k] = tv[k];
        mi[(col*4 + ng)*TOPK + k] = ti[k];
    }
    __syncthreads();
    if (ng == 0 && h < HW){
        int head[4];
        #pragma unroll
        for (int j=0;j<4;j++) head[j] = TOPK-1;
        float* cv = mv + col*4*TOPK;
        int*   ci = mi + col*4*TOPK;
        size_t base = (size_t)(((size_t)z*2 + b)*HW + h)*TOPK;
        #pragma unroll
        for (int k=0;k<TOPK;k++){
            float best = -3.4e38f; int bj = 0;
            #pragma unroll
            for (int j=0;j<4;j++){
                float v = cv[j*TOPK + head[j]];
                if (v > best){ best = v; bj = j; }
            }
            g_pv[base+k] = best;
            g_pi[base+k] = ci[bj*TOPK + head[bj]];
            head[bj]--;
        }
    }
}

// K4m: merge nsplit partial lists -> final top-20, softmax, expm1, scatter-add S.
template<int NS>
__global__ void k4_merge(int NE, int HW){
    int idx = blockIdx.x*blockDim.x + threadIdx.x;
    if (idx >= 2*HW) return;
    int b = idx / HW, h = idx - b*HW;
    int head[NS];
    #pragma unroll
    for (int j=0;j<NS;j++) head[j] = 0;
    float v[TOPK]; int id[TOPK];
    #pragma unroll
    for (int k=0;k<TOPK;k++){
        float best = -3.4e38f; int bj = 0;
        #pragma unroll
        for (int j=0;j<NS;j++){
            if (head[j] < TOPK){
                float x = g_pv[(size_t)(((size_t)j*2 + b)*HW + h)*TOPK + head[j]];
                if (x > best){ best = x; bj = j; }
            }
        }
        v[k] = best;
        id[k] = g_pi[(size_t)(((size_t)bj*2 + b)*HW + h)*TOPK + head[bj]];
        head[bj]++;
    }
    // softmax over merged (v[0] is max), scale by pos_w, expm1, scatter
    float m = v[0];
    float ssum = 0.f; float e[TOPK];
    #pragma unroll
    for (int k=0;k<TOPK;k++){ e[k] = expf(v[k]-m); ssum += e[k]; }
    float scale = g_pos[idx] / ssum;
    #pragma unroll
    for (int k=0;k<TOPK;k++){
        float em1 = expm1f(e[k]*scale);
        g_em1[(size_t)idx*TOPK + k] = em1;
        g_topi[(size_t)idx*TOPK + k] = id[k];
        atomicAdd(&g_S[b*NE + id[k]], em1);
    }
}

// K5: U[b,c] = sum_n vm[b,c,n] / S[b,n]
__global__ void __launch_bounds__(256) k5_U(const float* __restrict__ vm, int NE){
    int b = blockIdx.x >> 4;
    int c = blockIdx.x & 15;
    __shared__ float red[256];
    const float* p  = vm + ((size_t)b*16 + c)*NE;
    const float* Sp = g_S + b*NE;
    float s = 0.f;
    for (int n = threadIdx.x; n < NE; n += 256) s += p[n] / Sp[n];
    red[threadIdx.x] = s;
    __syncthreads();
    for (int st=128; st>=1; st>>=1){
        if (threadIdx.x < st) red[threadIdx.x] += red[threadIdx.x+st];
        __syncthreads();
    }
    if (threadIdx.x == 0) g_U[b*16+c] = red[0];
}

// K6: readout = U + sparse gather ; concat vq
__global__ void k6_out(const float* __restrict__ vm, const float* __restrict__ vq,
                       float* __restrict__ out, int NE, int HW){
    int idx = blockIdx.x*blockDim.x + threadIdx.x;
    if (idx >= 2*HW) return;
    int b = idx / HW, h = idx - b*HW;
    float acc[16];
    #pragma unroll
    for (int c=0;c<16;c++) acc[c] = g_U[b*16+c];
    #pragma unroll
    for (int k=0;k<TOPK;k++){
        int n = g_topi[(size_t)idx*TOPK + k];
        float f = g_em1[(size_t)idx*TOPK + k] / g_S[b*NE + n];
        const float* vp = vm + (size_t)b*16*NE + n;
        #pragma unroll
        for (int c=0;c<16;c++) acc[c] += vp[(size_t)c*NE]*f;
    }
    float* o = out + (size_t)b*32*HW + h;
    const float* v = vq + (size_t)b*16*HW + h;
    #pragma unroll
    for (int c=0;c<16;c++){
        o[(size_t)c*HW] = acc[c];
        o[(size_t)(16+c)*HW] = v[(size_t)c*HW];
    }
}

extern "C" void kernel_launch(void* const* d_in, const int* in_sizes, int n_in,
                              void* d_out, int out_size){
    const float* w1  = (const float*)d_in[12];
    const float* b1  = (const float*)d_in[13];
    const float* w2  = (const float*)d_in[14];
    const float* b2  = (const float*)d_in[15];
    const float* lg  = (const float*)d_in[16];
    const float* lb  = (const float*)d_in[17];
    const float* pw1 = (const float*)d_in[18];
    const float* pb1 = (const float*)d_in[19];
    const float* pw2 = (const float*)d_in[20];
    const float* pb2 = (const float*)d_in[21];

    k0_dummy<<<1, 32>>>();

    size_t ooff = 0;
    for (int i=0;i<3;i++){
        const float* kq = (const float*)d_in[i*4+0];
        const float* vq = (const float*)d_in[i*4+1];
        const float* km = (const float*)d_in[i*4+2];
        const float* vm = (const float*)d_in[i*4+3];
        int HW = in_sizes[i*4+0] / (2*64);   // [B=2, 64, H, W]
        int NE = in_sizes[i*4+2] / (2*64);   // [B=2, 64, NE]

        float* out = (float*)d_out + ooff;

        int gx = (HW + 31)/32;
        int nsplit = 1;
        while (nsplit < 16 && gx*2*nsplit < 296 && (NE/(nsplit*2)) >= 32) nsplit <<= 1;
        int chunk = ((NE + nsplit - 1)/nsplit + 31) & ~31;

        k1_prep<<<(2*NE + 255)/256, 256>>>(km, NE, HW);
        k2_posw<<<2, 256>>>(vq, w1,b1,w2,b2,lg,lb,pw1,pb1,pw2,pb2, HW, i);
        dim3 g3(gx, 2, nsplit);
        k3_topk<<<g3, 128>>>(kq, km, NE, HW, chunk);
        int thr = (2*HW + 127)/128;
        switch (nsplit){
            case 1:  k4_merge<1><<<thr,128>>>(NE,HW); break;
            case 2:  k4_merge<2><<<thr,128>>>(NE,HW); break;
            case 4:  k4_merge<4><<<thr,128>>>(NE,HW); break;
            case 8:  k4_merge<8><<<thr,128>>>(NE,HW); break;
            default: k4_merge<16><<<thr,128>>>(NE,HW); break;
        }
        k5_U<<<32, 256>>>(vm, NE);
        k6_out<<<(2*HW + 127)/128, 128>>>(vm, vq, out, NE, HW);

        ooff += (size_t)2*32*HW;
    }
}